// round 12
// baseline (speedup 1.0000x reference)
#include <cuda_runtime.h>
#include <cstdint>

// Problem constants (fixed by reference setup_inputs)
#define BATCH 128
#define SEQ   8192
#define FEAT  32
#define EVAL_POS 4096
#define TRAIN_ELEMS (EVAL_POS * FEAT)    // 131072 per batch
#define BATCH_ELEMS (SEQ * FEAT)         // 262144 per batch
#define TRAIN_VEC4  (TRAIN_ELEMS / 4)    // 32768 float4 per batch
#define BATCH_VEC4  (BATCH_ELEMS / 4)    // 65536 float4 per batch

#define FULL_MASK 0xFFFFu                // all 16 classes present

// Fused kernel, MLP=4 with loads AFTER the barrier:
//   - 64 blocks per batch, 256 threads, 4 float4 per thread
//     (64 * 256 * 4 = 65536 = BATCH_VEC4)
//   - Steady-state evidence: the only sub-45us dur came from the
//     loads-after-barrier pattern (R3). Hoisted variants front-batch the
//     block's bulk LDGs against the scan's prefix loads and consistently
//     cost one timer quantum in steady state despite better cold times.
//     This round pairs the after-barrier order with MLP=4's deeper rank-
//     phase pipeline (4 back-to-back LDG.128 per thread post-barrier).
//   - presence mask per batch via warp 0 with monotone-OR early exit
//     (correct for any input; saturates in ~2 iterations on this data;
//     all blocks of a batch read the same prefix bytes -> L2 hits).
//   - rank(v) = popc(mask & ((1<<v)-1)); __ldcs/__stcs streaming hints.
__global__ __launch_bounds__(256)
void fused_rank_kernel(const float4* __restrict__ x, float4* __restrict__ out)
{
    const int b = blockIdx.x >> 6;                 // 64 blocks per batch
    const size_t base = (size_t)b * BATCH_VEC4;

    __shared__ unsigned int s_mask;

    if (threadIdx.x < 32) {
        const float4* __restrict__ p = x + base;
        unsigned int m = 0;
        for (int i = threadIdx.x; i < TRAIN_VEC4; i += 32) {
            float4 v = __ldg(&p[i]);
            m |= 1u << (int)v.x;
            m |= 1u << (int)v.y;
            m |= 1u << (int)v.z;
            m |= 1u << (int)v.w;
            // warp-union early exit (safe: OR is monotone)
            if (__reduce_or_sync(0xffffffffu, m) == FULL_MASK) { m = FULL_MASK; break; }
        }
        m = __reduce_or_sync(0xffffffffu, m);
        if (threadIdx.x == 0) s_mask = m;
    }
    __syncthreads();
    const unsigned int mask = s_mask;

    // Rank phase: 1024 float4 per block, 4 per thread, issued back-to-back.
    const size_t i0 = base + ((size_t)(blockIdx.x & 63) << 10) + threadIdx.x;
    const size_t i1 = i0 + 256;
    const size_t i2 = i0 + 512;
    const size_t i3 = i0 + 768;

    float4 v0 = __ldcs(&x[i0]);
    float4 v1 = __ldcs(&x[i1]);
    float4 v2 = __ldcs(&x[i2]);
    float4 v3 = __ldcs(&x[i3]);

    float4 r0, r1, r2, r3;
    r0.x = (float)__popc(mask & ((1u << (int)v0.x) - 1u));
    r0.y = (float)__popc(mask & ((1u << (int)v0.y) - 1u));
    r0.z = (float)__popc(mask & ((1u << (int)v0.z) - 1u));
    r0.w = (float)__popc(mask & ((1u << (int)v0.w) - 1u));
    r1.x = (float)__popc(mask & ((1u << (int)v1.x) - 1u));
    r1.y = (float)__popc(mask & ((1u << (int)v1.y) - 1u));
    r1.z = (float)__popc(mask & ((1u << (int)v1.z) - 1u));
    r1.w = (float)__popc(mask & ((1u << (int)v1.w) - 1u));
    r2.x = (float)__popc(mask & ((1u << (int)v2.x) - 1u));
    r2.y = (float)__popc(mask & ((1u << (int)v2.y) - 1u));
    r2.z = (float)__popc(mask & ((1u << (int)v2.z) - 1u));
    r2.w = (float)__popc(mask & ((1u << (int)v2.w) - 1u));
    r3.x = (float)__popc(mask & ((1u << (int)v3.x) - 1u));
    r3.y = (float)__popc(mask & ((1u << (int)v3.y) - 1u));
    r3.z = (float)__popc(mask & ((1u << (int)v3.z) - 1u));
    r3.w = (float)__popc(mask & ((1u << (int)v3.w) - 1u));

    __stcs(&out[i0], r0);
    __stcs(&out[i1], r1);
    __stcs(&out[i2], r2);
    __stcs(&out[i3], r3);
}

extern "C" void kernel_launch(void* const* d_in, const int* in_sizes, int n_in,
                              void* d_out, int out_size)
{
    const float4* x  = (const float4*)d_in[0];   // [B, S, F] float32
    float4* out      = (float4*)d_out;           // [B, S, F] float32

    const int blocks = BATCH * 64;               // 8192
    fused_rank_kernel<<<blocks, 256>>>(x, out);
}

// round 13
// speedup vs baseline: 1.0270x; 1.0270x over previous
#include <cuda_runtime.h>
#include <cstdint>

// Problem constants (fixed by reference setup_inputs)
#define BATCH 128
#define SEQ   8192
#define FEAT  32
#define EVAL_POS 4096
#define TRAIN_ELEMS (EVAL_POS * FEAT)    // 131072 per batch
#define BATCH_ELEMS (SEQ * FEAT)         // 262144 per batch
#define TRAIN_VEC4  (TRAIN_ELEMS / 4)    // 32768 float4 per batch
#define BATCH_VEC4  (BATCH_ELEMS / 4)    // 65536 float4 per batch

#define FULL_MASK 0xFFFFu                // all 16 classes present

// Exact R3 body — the only configuration that has measured 43.68us.
// Fused kernel:
//   - 128 blocks per batch, 256 threads, 2 float4 per thread
//     (128 * 256 * 2 = 65536 = BATCH_VEC4)
//   - warp 0 computes the batch presence mask with early exit (monotone OR:
//     exiting when saturated is always safe). All blocks of a batch read the
//     same leading prefix bytes -> L2 hits; DRAM cost negligible.
//   - then every thread ranks its 2 float4 using popc on the masked prefix.
__global__ __launch_bounds__(256)
void fused_rank_kernel(const float4* __restrict__ x, float4* __restrict__ out)
{
    const int b = blockIdx.x >> 7;                 // 128 blocks per batch
    const size_t base = (size_t)b * BATCH_VEC4;

    __shared__ unsigned int s_mask;

    if (threadIdx.x < 32) {
        const float4* __restrict__ p = x + base;
        unsigned int m = 0;
        for (int i = threadIdx.x; i < TRAIN_VEC4; i += 32) {
            float4 v = __ldg(&p[i]);
            m |= 1u << (int)v.x;
            m |= 1u << (int)v.y;
            m |= 1u << (int)v.z;
            m |= 1u << (int)v.w;
            // warp-union early exit (safe: OR is monotone)
            if (__reduce_or_sync(0xffffffffu, m) == FULL_MASK) { m = FULL_MASK; break; }
        }
        m = __reduce_or_sync(0xffffffffu, m);
        if (threadIdx.x == 0) s_mask = m;
    }
    __syncthreads();
    const unsigned int mask = s_mask;

    // Rank phase: 512 float4 per block, 2 per thread, both loads in flight.
    const size_t i0 = base + ((size_t)(blockIdx.x & 127) << 9) + threadIdx.x;
    const size_t i1 = i0 + 256;

    float4 v0 = __ldcs(&x[i0]);
    float4 v1 = __ldcs(&x[i1]);

    float4 r0, r1;
    r0.x = (float)__popc(mask & ((1u << (int)v0.x) - 1u));
    r0.y = (float)__popc(mask & ((1u << (int)v0.y) - 1u));
    r0.z = (float)__popc(mask & ((1u << (int)v0.z) - 1u));
    r0.w = (float)__popc(mask & ((1u << (int)v0.w) - 1u));
    r1.x = (float)__popc(mask & ((1u << (int)v1.x) - 1u));
    r1.y = (float)__popc(mask & ((1u << (int)v1.y) - 1u));
    r1.z = (float)__popc(mask & ((1u << (int)v1.z) - 1u));
    r1.w = (float)__popc(mask & ((1u << (int)v1.w) - 1u));

    __stcs(&out[i0], r0);
    __stcs(&out[i1], r1);
}

extern "C" void kernel_launch(void* const* d_in, const int* in_sizes, int n_in,
                              void* d_out, int out_size)
{
    const float4* x  = (const float4*)d_in[0];   // [B, S, F] float32
    float4* out      = (float4*)d_out;           // [B, S, F] float32

    const int blocks = BATCH * 128;              // 16384
    fused_rank_kernel<<<blocks, 256>>>(x, out);
}